// round 6
// baseline (speedup 1.0000x reference)
#include <cuda_runtime.h>
#include <cstdint>
#include <cstddef>

#define B_SZ 256
#define NTOK 196
#define C_DIM 512
#define NH 8
#define KD 32
#define DV 128
#define DH 1024
#define HQKV 1536
#define QT 49
#define SCALE 0.17677669529663687f

// padded attention dims
#define MP 64          // padded query rows per q-tile
#define NP 224         // padded key count
#define PS 228         // sS pitch (fp32)  : 228 % 32 == 4  -> conflict-free
#define PQ 36          // sq/sk pitch (u32): 36 % 32  == 4  -> conflict-free
#define PVP 136        // sv pitch (u32)   : 136 % 32 == 8  -> conflict-free

// Scratch buffers (device globals: allocation-free rule)
__device__ float g_qkv[(size_t)B_SZ * NTOK * HQKV];     // [B, N, 1536]
__device__ float g_att[(size_t)B_SZ * NTOK * DH];       // [B, N, 1024]
__device__ float g_bmat[(size_t)NH * NTOK * NTOK];      // [8, 196, 196]

__device__ __forceinline__ uint32_t f2tf32(float x) {
    uint32_t r;
    asm("cvt.rna.tf32.f32 %0, %1;" : "=r"(r) : "f"(x));
    return r;
}

__device__ __forceinline__ void mma_tf32(float* d, const uint32_t* a, const uint32_t* b) {
    asm volatile(
        "mma.sync.aligned.m16n8k8.row.col.f32.tf32.tf32.f32 "
        "{%0,%1,%2,%3}, {%4,%5,%6,%7}, {%8,%9}, {%0,%1,%2,%3};\n"
        : "+f"(d[0]), "+f"(d[1]), "+f"(d[2]), "+f"(d[3])
        : "r"(a[0]), "r"(a[1]), "r"(a[2]), "r"(a[3]),
          "r"(b[0]), "r"(b[1]));
}

// ---------------------------------------------------------------------------
// bmat[h][i][j] = attention_biases[h][bias_idxs[i][j]]
// ---------------------------------------------------------------------------
__global__ void bias_precompute(const float* __restrict__ ab,
                                const int* __restrict__ bidx,
                                float* __restrict__ bmat, int n_off)
{
    int idx = blockIdx.x * 256 + threadIdx.x;
    if (idx >= NH * NTOK * NTOK) return;
    int h  = idx / (NTOK * NTOK);
    int ij = idx % (NTOK * NTOK);
    bmat[idx] = ab[h * n_off + bidx[ij]];
}

// ---------------------------------------------------------------------------
// C[M,N] = A[M,K] @ W[N,K]^T + bias[N]  via tf32 mma.sync. (unchanged)
// ---------------------------------------------------------------------------
__global__ void __launch_bounds__(256, 2)
gemm_tf32_bias(const float* __restrict__ A, const float* __restrict__ W,
               const float* __restrict__ bias, float* __restrict__ C,
               int M, int N, int K)
{
    __shared__ uint32_t As[128 * 36];
    __shared__ uint32_t Bs[128 * 36];

    const int tid  = threadIdx.x;
    const int lane = tid & 31;
    const int wid  = tid >> 5;
    const int warpM = wid >> 2;
    const int warpN = wid & 3;
    const int g = lane >> 2;
    const int c = lane & 3;
    const int m0 = blockIdx.y * 128;
    const int n0 = blockIdx.x * 128;

    float acc[4][4][4];
    #pragma unroll
    for (int mt = 0; mt < 4; mt++)
        #pragma unroll
        for (int nt = 0; nt < 4; nt++)
            #pragma unroll
            for (int e = 0; e < 4; e++) acc[mt][nt][e] = 0.f;

    for (int kk = 0; kk < K; kk += 32) {
        #pragma unroll
        for (int it = 0; it < 4; it++) {
            int idx = tid + it * 256;
            int row = idx >> 3;
            int col = (idx & 7) << 2;
            float4 av = *(const float4*)(A + (size_t)(m0 + row) * K + kk + col);
            float4 wv = *(const float4*)(W + (size_t)(n0 + row) * K + kk + col);
            uint32_t* ap = As + row * 36 + col;
            ap[0] = f2tf32(av.x); ap[1] = f2tf32(av.y);
            ap[2] = f2tf32(av.z); ap[3] = f2tf32(av.w);
            uint32_t* bp = Bs + row * 36 + col;
            bp[0] = f2tf32(wv.x); bp[1] = f2tf32(wv.y);
            bp[2] = f2tf32(wv.z); bp[3] = f2tf32(wv.w);
        }
        __syncthreads();

        #pragma unroll
        for (int ks = 0; ks < 4; ks++) {
            const int kb = ks * 8;
            uint32_t af[4][4], bf[4][2];
            #pragma unroll
            for (int mt = 0; mt < 4; mt++) {
                int rb = warpM * 64 + mt * 16;
                const uint32_t* p0 = As + (rb + g) * 36 + kb + c;
                const uint32_t* p1 = As + (rb + g + 8) * 36 + kb + c;
                af[mt][0] = p0[0];
                af[mt][1] = p1[0];
                af[mt][2] = p0[4];
                af[mt][3] = p1[4];
            }
            #pragma unroll
            for (int nt = 0; nt < 4; nt++) {
                int nb = warpN * 32 + nt * 8;
                const uint32_t* p = Bs + (nb + g) * 36 + kb + c;
                bf[nt][0] = p[0];
                bf[nt][1] = p[4];
            }
            #pragma unroll
            for (int mt = 0; mt < 4; mt++)
                #pragma unroll
                for (int nt = 0; nt < 4; nt++)
                    mma_tf32(acc[mt][nt], af[mt], bf[nt]);
        }
        __syncthreads();
    }

    #pragma unroll
    for (int mt = 0; mt < 4; mt++) {
        int r0 = m0 + warpM * 64 + mt * 16 + g;
        #pragma unroll
        for (int nt = 0; nt < 4; nt++) {
            int col = n0 + warpN * 32 + nt * 8 + 2 * c;
            float b0 = bias[col], b1 = bias[col + 1];
            float* cp0 = C + (size_t)r0 * N + col;
            float* cp1 = C + (size_t)(r0 + 8) * N + col;
            *(float2*)cp0 = make_float2(acc[mt][nt][0] + b0, acc[mt][nt][1] + b1);
            *(float2*)cp1 = make_float2(acc[mt][nt][2] + b0, acc[mt][nt][3] + b1);
        }
    }
}

// ---------------------------------------------------------------------------
// Resident-KV tensor-core attention. One CTA of 512 threads per (head, batch).
// K [224][32] and V [224][128] staged ONCE in smem; the 4 q-tiles of 49
// queries are processed sequentially (S = QK^T, softmax+bias, O = PV).
// smem (u32 words): sS 64*228 | sq 64*36 | sk 224*36 | sv 224*136  = 216.5 KB
// ---------------------------------------------------------------------------
__global__ void __launch_bounds__(512, 1)
attn_mma(const float* __restrict__ qkv, const float* __restrict__ bmat,
         float* __restrict__ attn_out)
{
    extern __shared__ uint32_t smu[];
    float*    sS = (float*)smu;                  // 64*228 = 14592
    uint32_t* sq = smu + MP * PS;                // 64*36  = 2304
    uint32_t* sk = sq + MP * PQ;                 // 224*36 = 8064
    uint32_t* sv = sk + NP * PQ;                 // 224*136= 30464

    const int tid  = threadIdx.x;
    const int lane = tid & 31;
    const int wid  = tid >> 5;          // 0..15
    const int g = lane >> 2;
    const int c = lane & 3;
    const int warpM = wid >> 2;         // 0..3 -> 16 rows each
    const int warpN = wid & 3;          // 0..3
    const int h  = blockIdx.x;
    const int b  = blockIdx.y;
    const float* base = qkv + (size_t)b * NTOK * HQKV + h * (2 * KD + DV);

    // ---- stage K [224][32] (rows >=196 zero), tf32 ----
    for (int i = tid; i < NP * 8; i += 512) {
        int r = i >> 3, cc = (i & 7) << 2;
        uint32_t* d = sk + r * PQ + cc;
        if (r < NTOK) {
            float4 v = *(const float4*)(base + (size_t)r * HQKV + KD + cc);
            d[0] = f2tf32(v.x); d[1] = f2tf32(v.y); d[2] = f2tf32(v.z); d[3] = f2tf32(v.w);
        } else { d[0] = 0u; d[1] = 0u; d[2] = 0u; d[3] = 0u; }
    }
    // ---- stage V [224][128] k-major (rows >=196 zero), tf32 ----
    for (int i = tid; i < NP * 32; i += 512) {
        int r = i >> 5, cc = (i & 31) << 2;
        uint32_t* d = sv + r * PVP + cc;
        if (r < NTOK) {
            float4 v = *(const float4*)(base + (size_t)r * HQKV + 2 * KD + cc);
            d[0] = f2tf32(v.x); d[1] = f2tf32(v.y); d[2] = f2tf32(v.z); d[3] = f2tf32(v.w);
        } else { d[0] = 0u; d[1] = 0u; d[2] = 0u; d[3] = 0u; }
    }

    const int m0 = warpM * 16;

    for (int qt = 0; qt < 4; qt++) {
        // ---- stage Q tile [64][32] (rows >=49 zero) ----
        {
            int i = tid;                        // exactly 512 float4 slots
            int r = i >> 3, cc = (i & 7) << 2;
            uint32_t* d = sq + r * PQ + cc;
            if (r < QT) {
                float4 v = *(const float4*)(base + (size_t)(qt * QT + r) * HQKV + cc);
                d[0] = f2tf32(v.x); d[1] = f2tf32(v.y); d[2] = f2tf32(v.z); d[3] = f2tf32(v.w);
            } else { d[0] = 0u; d[1] = 0u; d[2] = 0u; d[3] = 0u; }
        }
        __syncthreads();   // K,V,Q ready; prior PV (reads sS) finished

        // ---- S = Q K^T : warp tile 16 x 56 (7 n-tiles), 4 k-steps ----
        {
            float accS[7][4];
            #pragma unroll
            for (int nt = 0; nt < 7; nt++)
                #pragma unroll
                for (int e = 0; e < 4; e++) accS[nt][e] = 0.f;

            #pragma unroll
            for (int ks = 0; ks < 4; ks++) {
                const int kb = ks * 8;
                uint32_t a[4];
                const uint32_t* p0 = sq + (m0 + g) * PQ + kb + c;
                const uint32_t* p1 = sq + (m0 + g + 8) * PQ + kb + c;
                a[0] = p0[0]; a[1] = p1[0]; a[2] = p0[4]; a[3] = p1[4];
                #pragma unroll
                for (int nt = 0; nt < 7; nt++) {
                    int nb = warpN * 56 + nt * 8;
                    const uint32_t* p = sk + (nb + g) * PQ + kb + c;
                    uint32_t bfr[2] = {p[0], p[4]};
                    mma_tf32(accS[nt], a, bfr);
                }
            }
            #pragma unroll
            for (int nt = 0; nt < 7; nt++) {
                int row = m0 + g;
                int col = warpN * 56 + nt * 8 + 2 * c;
                *(float2*)(sS + row * PS + col) = make_float2(accS[nt][0], accS[nt][1]);
                *(float2*)(sS + (row + 8) * PS + col) = make_float2(accS[nt][2], accS[nt][3]);
            }
        }
        __syncthreads();

        // ---- softmax rows 0..48, cols 0..195 ----
        for (int r = wid; r < QT; r += 16) {
            const float* brow = bmat + ((size_t)h * NTOK + qt * QT + r) * NTOK;
            float* srow = sS + r * PS;
            float mx = -3.0e38f;
            for (int cc = lane; cc < NTOK; cc += 32) {
                float v = srow[cc] * SCALE + brow[cc];
                srow[cc] = v;
                mx = fmaxf(mx, v);
            }
            #pragma unroll
            for (int o = 16; o; o >>= 1) mx = fmaxf(mx, __shfl_xor_sync(0xffffffffu, mx, o));
            float sum = 0.f;
            for (int cc = lane; cc < NTOK; cc += 32) {
                float e = __expf(srow[cc] - mx);
                srow[cc] = e;
                sum += e;
            }
            #pragma unroll
            for (int o = 16; o; o >>= 1) sum += __shfl_xor_sync(0xffffffffu, sum, o);
            float inv = 1.f / sum;
            for (int cc = lane; cc < NTOK; cc += 32) srow[cc] *= inv;
        }
        __syncthreads();

        // ---- O = P V : warp tile 16 x 32 (4 n-tiles), 28 k-steps ----
        {
            float accO[4][4];
            #pragma unroll
            for (int nt = 0; nt < 4; nt++)
                #pragma unroll
                for (int e = 0; e < 4; e++) accO[nt][e] = 0.f;

            const int nb0 = warpN * 32;
            #pragma unroll 4
            for (int ks = 0; ks < 28; ks++) {
                const int kl = ks * 8;
                uint32_t a[4];
                const float* q0 = sS + (m0 + g) * PS + kl + c;
                const float* q1 = sS + (m0 + g + 8) * PS + kl + c;
                a[0] = f2tf32(q0[0]); a[1] = f2tf32(q1[0]);
                a[2] = f2tf32(q0[4]); a[3] = f2tf32(q1[4]);
                #pragma unroll
                for (int nt = 0; nt < 4; nt++) {
                    int nb = nb0 + nt * 8;
                    uint32_t bfr[2];
                    bfr[0] = sv[(kl + c) * PVP + nb + g];
                    bfr[1] = sv[(kl + c + 4) * PVP + nb + g];
                    mma_tf32(accO[nt], a, bfr);
                }
            }

            // ---- store O rows < 49 ----
            int r1 = m0 + g;
            int r2 = r1 + 8;
            const size_t ob = ((size_t)b * NTOK + qt * QT) * DH + h * DV;
            #pragma unroll
            for (int nt = 0; nt < 4; nt++) {
                int col = nb0 + nt * 8 + 2 * c;
                if (r1 < QT)
                    *(float2*)(attn_out + ob + (size_t)r1 * DH + col) =
                        make_float2(accO[nt][0], accO[nt][1]);
                if (r2 < QT)
                    *(float2*)(attn_out + ob + (size_t)r2 * DH + col) =
                        make_float2(accO[nt][2], accO[nt][3]);
            }
        }
    }
}

// ---------------------------------------------------------------------------
extern "C" void kernel_launch(void* const* d_in, const int* in_sizes, int n_in,
                              void* d_out, int out_size)
{
    const float* x      = (const float*)d_in[0];
    const float* qkv_w  = (const float*)d_in[1];
    const float* qkv_b  = (const float*)d_in[2];
    const float* proj_w = (const float*)d_in[3];
    const float* proj_b = (const float*)d_in[4];
    const float* ab     = (const float*)d_in[5];
    const int*   bidx   = (const int*)d_in[6];
    float* out = (float*)d_out;
    const int n_off = in_sizes[5] / NH;

    float *qkv_buf, *att_buf, *bmat;
    cudaGetSymbolAddress((void**)&qkv_buf, g_qkv);
    cudaGetSymbolAddress((void**)&att_buf, g_att);
    cudaGetSymbolAddress((void**)&bmat, g_bmat);

    const int ATTN_SMEM = (MP * PS + MP * PQ + NP * PQ + NP * PVP) * (int)sizeof(uint32_t);
    cudaFuncSetAttribute(attn_mma, cudaFuncAttributeMaxDynamicSharedMemorySize, ATTN_SMEM);

    const int M = B_SZ * NTOK;  // 50176

    // 0) bias matrix precompute (batch-invariant, tiny)
    bias_precompute<<<(NH * NTOK * NTOK + 255) / 256, 256>>>(ab, bidx, bmat, n_off);
    // 1) QKV = x @ qkv_w^T + qkv_b
    gemm_tf32_bias<<<dim3(HQKV / 128, M / 128), 256>>>(x, qkv_w, qkv_b, qkv_buf,
                                                       M, HQKV, C_DIM);
    // 2) attention: one CTA per (head, batch), K/V resident
    attn_mma<<<dim3(NH, B_SZ), 512, ATTN_SMEM>>>(qkv_buf, bmat, att_buf);
    // 3) out = att @ proj_w^T + proj_b
    gemm_tf32_bias<<<dim3(C_DIM / 128, M / 128), 256>>>(att_buf, proj_w, proj_b, out,
                                                        M, C_DIM, DH);
}

// round 7
// speedup vs baseline: 1.0083x; 1.0083x over previous
#include <cuda_runtime.h>
#include <cstdint>
#include <cstddef>

#define B_SZ 256
#define NTOK 196
#define C_DIM 512
#define NH 8
#define KD 32
#define DV 128
#define DH 1024
#define HQKV 1536
#define QT 49
#define SCALE 0.17677669529663687f

// padded attention dims
#define MP 64          // padded query rows per q-tile
#define NP 224         // padded key count
#define PS 228         // sS pitch (fp32)  : 228 % 32 == 4  -> conflict-free
#define PQ 36          // sq/sk pitch (u32): 36 % 32  == 4  -> conflict-free
#define PVP 136        // sv pitch (u32)   : 136 % 32 == 8  -> conflict-free

// Scratch buffers (device globals: allocation-free rule)
__device__ float g_qkv[(size_t)B_SZ * NTOK * HQKV];     // [B, N, 1536]
__device__ float g_att[(size_t)B_SZ * NTOK * DH];       // [B, N, 1024]
__device__ float g_bmat[(size_t)NH * NTOK * NTOK];      // [8, 196, 196]

__device__ __forceinline__ uint32_t f2tf32(float x) {
    uint32_t r;
    asm("cvt.rna.tf32.f32 %0, %1;" : "=r"(r) : "f"(x));
    return r;
}

__device__ __forceinline__ void mma_tf32(float* d, const uint32_t* a, const uint32_t* b) {
    asm volatile(
        "mma.sync.aligned.m16n8k8.row.col.f32.tf32.tf32.f32 "
        "{%0,%1,%2,%3}, {%4,%5,%6,%7}, {%8,%9}, {%0,%1,%2,%3};\n"
        : "+f"(d[0]), "+f"(d[1]), "+f"(d[2]), "+f"(d[3])
        : "r"(a[0]), "r"(a[1]), "r"(a[2]), "r"(a[3]),
          "r"(b[0]), "r"(b[1]));
}

// ---------------------------------------------------------------------------
// bmat[h][i][j] = attention_biases[h][bias_idxs[i][j]]
// ---------------------------------------------------------------------------
__global__ void bias_precompute(const float* __restrict__ ab,
                                const int* __restrict__ bidx,
                                float* __restrict__ bmat, int n_off)
{
    int idx = blockIdx.x * 256 + threadIdx.x;
    if (idx >= NH * NTOK * NTOK) return;
    int h  = idx / (NTOK * NTOK);
    int ij = idx % (NTOK * NTOK);
    bmat[idx] = ab[h * n_off + bidx[ij]];
}

// ---------------------------------------------------------------------------
// C[M,N] = A[M,K] @ W[N,K]^T + bias[N]  via tf32 mma.sync. (unchanged)
// ---------------------------------------------------------------------------
__global__ void __launch_bounds__(256, 2)
gemm_tf32_bias(const float* __restrict__ A, const float* __restrict__ W,
               const float* __restrict__ bias, float* __restrict__ C,
               int M, int N, int K)
{
    __shared__ uint32_t As[128 * 36];
    __shared__ uint32_t Bs[128 * 36];

    const int tid  = threadIdx.x;
    const int lane = tid & 31;
    const int wid  = tid >> 5;
    const int warpM = wid >> 2;
    const int warpN = wid & 3;
    const int g = lane >> 2;
    const int c = lane & 3;
    const int m0 = blockIdx.y * 128;
    const int n0 = blockIdx.x * 128;

    float acc[4][4][4];
    #pragma unroll
    for (int mt = 0; mt < 4; mt++)
        #pragma unroll
        for (int nt = 0; nt < 4; nt++)
            #pragma unroll
            for (int e = 0; e < 4; e++) acc[mt][nt][e] = 0.f;

    for (int kk = 0; kk < K; kk += 32) {
        #pragma unroll
        for (int it = 0; it < 4; it++) {
            int idx = tid + it * 256;
            int row = idx >> 3;
            int col = (idx & 7) << 2;
            float4 av = *(const float4*)(A + (size_t)(m0 + row) * K + kk + col);
            float4 wv = *(const float4*)(W + (size_t)(n0 + row) * K + kk + col);
            uint32_t* ap = As + row * 36 + col;
            ap[0] = f2tf32(av.x); ap[1] = f2tf32(av.y);
            ap[2] = f2tf32(av.z); ap[3] = f2tf32(av.w);
            uint32_t* bp = Bs + row * 36 + col;
            bp[0] = f2tf32(wv.x); bp[1] = f2tf32(wv.y);
            bp[2] = f2tf32(wv.z); bp[3] = f2tf32(wv.w);
        }
        __syncthreads();

        #pragma unroll
        for (int ks = 0; ks < 4; ks++) {
            const int kb = ks * 8;
            uint32_t af[4][4], bf[4][2];
            #pragma unroll
            for (int mt = 0; mt < 4; mt++) {
                int rb = warpM * 64 + mt * 16;
                const uint32_t* p0 = As + (rb + g) * 36 + kb + c;
                const uint32_t* p1 = As + (rb + g + 8) * 36 + kb + c;
                af[mt][0] = p0[0];
                af[mt][1] = p1[0];
                af[mt][2] = p0[4];
                af[mt][3] = p1[4];
            }
            #pragma unroll
            for (int nt = 0; nt < 4; nt++) {
                int nb = warpN * 32 + nt * 8;
                const uint32_t* p = Bs + (nb + g) * 36 + kb + c;
                bf[nt][0] = p[0];
                bf[nt][1] = p[4];
            }
            #pragma unroll
            for (int mt = 0; mt < 4; mt++)
                #pragma unroll
                for (int nt = 0; nt < 4; nt++)
                    mma_tf32(acc[mt][nt], af[mt], bf[nt]);
        }
        __syncthreads();
    }

    #pragma unroll
    for (int mt = 0; mt < 4; mt++) {
        int r0 = m0 + warpM * 64 + mt * 16 + g;
        #pragma unroll
        for (int nt = 0; nt < 4; nt++) {
            int col = n0 + warpN * 32 + nt * 8 + 2 * c;
            float b0 = bias[col], b1 = bias[col + 1];
            float* cp0 = C + (size_t)r0 * N + col;
            float* cp1 = C + (size_t)(r0 + 8) * N + col;
            *(float2*)cp0 = make_float2(acc[mt][nt][0] + b0, acc[mt][nt][1] + b1);
            *(float2*)cp1 = make_float2(acc[mt][nt][2] + b0, acc[mt][nt][3] + b1);
        }
    }
}

// ---------------------------------------------------------------------------
// Resident-KV tensor-core attention. One CTA of 512 threads per (head, batch).
// K [224][32] and V [224][128] staged ONCE in smem; the 4 q-tiles of 49
// queries are processed sequentially (S = QK^T, softmax+bias, O = PV).
// smem (u32 words): sS 64*228 | sq 64*36 | sk 224*36 | sv 224*136  = 216.5 KB
// ---------------------------------------------------------------------------
__global__ void __launch_bounds__(512, 1)
attn_mma(const float* __restrict__ qkv, const float* __restrict__ bmat,
         float* __restrict__ attn_out)
{
    extern __shared__ uint32_t smu[];
    float*    sS = (float*)smu;                  // 64*228 = 14592
    uint32_t* sq = smu + MP * PS;                // 64*36  = 2304
    uint32_t* sk = sq + MP * PQ;                 // 224*36 = 8064
    uint32_t* sv = sk + NP * PQ;                 // 224*136= 30464

    const int tid  = threadIdx.x;
    const int lane = tid & 31;
    const int wid  = tid >> 5;          // 0..15
    const int g = lane >> 2;
    const int c = lane & 3;
    const int warpM = wid >> 2;         // 0..3 -> 16 rows each
    const int warpN = wid & 3;          // 0..3
    const int h  = blockIdx.x;
    const int b  = blockIdx.y;
    const float* base = qkv + (size_t)b * NTOK * HQKV + h * (2 * KD + DV);

    // ---- stage K [224][32] (rows >=196 zero), tf32 ----
    for (int i = tid; i < NP * 8; i += 512) {
        int r = i >> 3, cc = (i & 7) << 2;
        uint32_t* d = sk + r * PQ + cc;
        if (r < NTOK) {
            float4 v = *(const float4*)(base + (size_t)r * HQKV + KD + cc);
            d[0] = f2tf32(v.x); d[1] = f2tf32(v.y); d[2] = f2tf32(v.z); d[3] = f2tf32(v.w);
        } else { d[0] = 0u; d[1] = 0u; d[2] = 0u; d[3] = 0u; }
    }
    // ---- stage V [224][128] k-major (rows >=196 zero), tf32 ----
    for (int i = tid; i < NP * 32; i += 512) {
        int r = i >> 5, cc = (i & 31) << 2;
        uint32_t* d = sv + r * PVP + cc;
        if (r < NTOK) {
            float4 v = *(const float4*)(base + (size_t)r * HQKV + 2 * KD + cc);
            d[0] = f2tf32(v.x); d[1] = f2tf32(v.y); d[2] = f2tf32(v.z); d[3] = f2tf32(v.w);
        } else { d[0] = 0u; d[1] = 0u; d[2] = 0u; d[3] = 0u; }
    }

    const int m0 = warpM * 16;

    for (int qt = 0; qt < 4; qt++) {
        // ---- stage Q tile [64][32] (rows >=49 zero) ----
        {
            int i = tid;                        // exactly 512 float4 slots
            int r = i >> 3, cc = (i & 7) << 2;
            uint32_t* d = sq + r * PQ + cc;
            if (r < QT) {
                float4 v = *(const float4*)(base + (size_t)(qt * QT + r) * HQKV + cc);
                d[0] = f2tf32(v.x); d[1] = f2tf32(v.y); d[2] = f2tf32(v.z); d[3] = f2tf32(v.w);
            } else { d[0] = 0u; d[1] = 0u; d[2] = 0u; d[3] = 0u; }
        }
        __syncthreads();   // K,V,Q ready; prior PV (reads sS) finished

        // ---- S = Q K^T : warp tile 16 x 56 (7 n-tiles), 4 k-steps ----
        {
            float accS[7][4];
            #pragma unroll
            for (int nt = 0; nt < 7; nt++)
                #pragma unroll
                for (int e = 0; e < 4; e++) accS[nt][e] = 0.f;

            #pragma unroll
            for (int ks = 0; ks < 4; ks++) {
                const int kb = ks * 8;
                uint32_t a[4];
                const uint32_t* p0 = sq + (m0 + g) * PQ + kb + c;
                const uint32_t* p1 = sq + (m0 + g + 8) * PQ + kb + c;
                a[0] = p0[0]; a[1] = p1[0]; a[2] = p0[4]; a[3] = p1[4];
                #pragma unroll
                for (int nt = 0; nt < 7; nt++) {
                    int nb = warpN * 56 + nt * 8;
                    const uint32_t* p = sk + (nb + g) * PQ + kb + c;
                    uint32_t bfr[2] = {p[0], p[4]};
                    mma_tf32(accS[nt], a, bfr);
                }
            }
            #pragma unroll
            for (int nt = 0; nt < 7; nt++) {
                int row = m0 + g;
                int col = warpN * 56 + nt * 8 + 2 * c;
                *(float2*)(sS + row * PS + col) = make_float2(accS[nt][0], accS[nt][1]);
                *(float2*)(sS + (row + 8) * PS + col) = make_float2(accS[nt][2], accS[nt][3]);
            }
        }
        __syncthreads();

        // ---- softmax rows 0..48, cols 0..195 ----
        for (int r = wid; r < QT; r += 16) {
            const float* brow = bmat + ((size_t)h * NTOK + qt * QT + r) * NTOK;
            float* srow = sS + r * PS;
            float mx = -3.0e38f;
            for (int cc = lane; cc < NTOK; cc += 32) {
                float v = srow[cc] * SCALE + brow[cc];
                srow[cc] = v;
                mx = fmaxf(mx, v);
            }
            #pragma unroll
            for (int o = 16; o; o >>= 1) mx = fmaxf(mx, __shfl_xor_sync(0xffffffffu, mx, o));
            float sum = 0.f;
            for (int cc = lane; cc < NTOK; cc += 32) {
                float e = __expf(srow[cc] - mx);
                srow[cc] = e;
                sum += e;
            }
            #pragma unroll
            for (int o = 16; o; o >>= 1) sum += __shfl_xor_sync(0xffffffffu, sum, o);
            float inv = 1.f / sum;
            for (int cc = lane; cc < NTOK; cc += 32) srow[cc] *= inv;
        }
        __syncthreads();

        // ---- O = P V : warp tile 16 x 32 (4 n-tiles), 28 k-steps ----
        {
            float accO[4][4];
            #pragma unroll
            for (int nt = 0; nt < 4; nt++)
                #pragma unroll
                for (int e = 0; e < 4; e++) accO[nt][e] = 0.f;

            const int nb0 = warpN * 32;
            #pragma unroll 4
            for (int ks = 0; ks < 28; ks++) {
                const int kl = ks * 8;
                uint32_t a[4];
                const float* q0 = sS + (m0 + g) * PS + kl + c;
                const float* q1 = sS + (m0 + g + 8) * PS + kl + c;
                a[0] = f2tf32(q0[0]); a[1] = f2tf32(q1[0]);
                a[2] = f2tf32(q0[4]); a[3] = f2tf32(q1[4]);
                #pragma unroll
                for (int nt = 0; nt < 4; nt++) {
                    int nb = nb0 + nt * 8;
                    uint32_t bfr[2];
                    bfr[0] = sv[(kl + c) * PVP + nb + g];
                    bfr[1] = sv[(kl + c + 4) * PVP + nb + g];
                    mma_tf32(accO[nt], a, bfr);
                }
            }

            // ---- store O rows < 49 ----
            int r1 = m0 + g;
            int r2 = r1 + 8;
            const size_t ob = ((size_t)b * NTOK + qt * QT) * DH + h * DV;
            #pragma unroll
            for (int nt = 0; nt < 4; nt++) {
                int col = nb0 + nt * 8 + 2 * c;
                if (r1 < QT)
                    *(float2*)(attn_out + ob + (size_t)r1 * DH + col) =
                        make_float2(accO[nt][0], accO[nt][1]);
                if (r2 < QT)
                    *(float2*)(attn_out + ob + (size_t)r2 * DH + col) =
                        make_float2(accO[nt][2], accO[nt][3]);
            }
        }
    }
}

// ---------------------------------------------------------------------------
extern "C" void kernel_launch(void* const* d_in, const int* in_sizes, int n_in,
                              void* d_out, int out_size)
{
    const float* x      = (const float*)d_in[0];
    const float* qkv_w  = (const float*)d_in[1];
    const float* qkv_b  = (const float*)d_in[2];
    const float* proj_w = (const float*)d_in[3];
    const float* proj_b = (const float*)d_in[4];
    const float* ab     = (const float*)d_in[5];
    const int*   bidx   = (const int*)d_in[6];
    float* out = (float*)d_out;
    const int n_off = in_sizes[5] / NH;

    float *qkv_buf, *att_buf, *bmat;
    cudaGetSymbolAddress((void**)&qkv_buf, g_qkv);
    cudaGetSymbolAddress((void**)&att_buf, g_att);
    cudaGetSymbolAddress((void**)&bmat, g_bmat);

    const int ATTN_SMEM = (MP * PS + MP * PQ + NP * PQ + NP * PVP) * (int)sizeof(uint32_t);
    cudaFuncSetAttribute(attn_mma, cudaFuncAttributeMaxDynamicSharedMemorySize, ATTN_SMEM);

    const int M = B_SZ * NTOK;  // 50176

    // 0) bias matrix precompute (batch-invariant, tiny)
    bias_precompute<<<(NH * NTOK * NTOK + 255) / 256, 256>>>(ab, bidx, bmat, n_off);
    // 1) QKV = x @ qkv_w^T + qkv_b
    gemm_tf32_bias<<<dim3(HQKV / 128, M / 128), 256>>>(x, qkv_w, qkv_b, qkv_buf,
                                                       M, HQKV, C_DIM);
    // 2) attention: one CTA per (head, batch), K/V resident
    attn_mma<<<dim3(NH, B_SZ), 512, ATTN_SMEM>>>(qkv_buf, bmat, att_buf);
    // 3) out = att @ proj_w^T + proj_b
    gemm_tf32_bias<<<dim3(C_DIM / 128, M / 128), 256>>>(att_buf, proj_w, proj_b, out,
                                                        M, C_DIM, DH);
}